// round 4
// baseline (speedup 1.0000x reference)
#include <cuda_runtime.h>
#include <math.h>

#define NCLS   20
#define NANC   5
#define NB_    64
#define NH_    38
#define NW_    38
#define MAXB_  50
#define SPATIAL 1444
#define CPB    7220            // NANC*SPATIAL
#define NGRP   (CPB / 4)       // 1805 groups of 4 cells
#define NCH    25
#define OBJ_   5.0f
#define K_     0.375f          // THRESH/(1+THRESH) = 0.6/1.6
#define TPB    128
#define GRIDX  15              // ceil(1805/128)
#define NBLK   (GRIDX * NB_)   // 960 blocks

// Last-block aggregation state (zero-initialized at load; reset each call)
__device__ float        g_acc = 0.0f;
__device__ unsigned int g_cnt = 0;

__device__ __forceinline__ float sigm(float v) { return 1.0f / (1.0f + __expf(-v)); }

__device__ __forceinline__ float iou_full(float x1, float y1, float w1, float h1,
                                          float x2, float y2, float w2, float h2) {
    float cw = fminf(x1 + 0.5f * w1, x2 + 0.5f * w2) - fmaxf(x1 - 0.5f * w1, x2 - 0.5f * w2);
    float ch = fminf(y1 + 0.5f * h1, y2 + 0.5f * h2) - fmaxf(y1 - 0.5f * h1, y2 - 0.5f * h2);
    float inter = (cw <= 0.0f || ch <= 0.0f) ? 0.0f : cw * ch;
    float uni = w1 * h1 + w2 * h2 - inter;
    return inter / uni;
}

__global__ void __launch_bounds__(TPB)
region_fused(const float* __restrict__ out,
             const float* __restrict__ tgt,
             const float* __restrict__ anc,
             float* __restrict__ res) {
    const int b = blockIdx.y;
    const int tid = threadIdx.x;

    __shared__ int    s_nv;
    __shared__ float4 s_b4[MAXB_ + 4];
    __shared__ float  s_g2[MAXB_ + 4];
    __shared__ int    s_cell[MAXB_];

    // ---- Issue the big loads FIRST so they overlap the target parse ----
    const int group = blockIdx.x * TPB + tid;
    const bool act = (group < NGRP);
    int a = 0, rem = 0, i0 = 0, j0 = 0;
    float4 v0, v1, v2, v3, v4;
    float aw0 = 0, ah0 = 0;
    if (act) {
        int base = group * 4;
        a = base / SPATIAL;
        rem = base - a * SPATIAL;
        j0 = rem / NW_;
        i0 = rem - j0 * NW_;
        const float* op = out + ((size_t)(b * NANC + a)) * NCH * SPATIAL + rem;
        v0 = *(const float4*)(op);
        v1 = *(const float4*)(op + SPATIAL);
        v2 = *(const float4*)(op + 2 * SPATIAL);
        v3 = *(const float4*)(op + 3 * SPATIAL);
        v4 = *(const float4*)(op + 4 * SPATIAL);
        aw0 = __ldg(&anc[2 * a]);
        ah0 = __ldg(&anc[2 * a + 1]);
    }

    // ---- Parallel target parse ----
    if (tid == 0) s_nv = MAXB_;
    __syncthreads();
    float tp1 = 0.0f;
    if (tid < MAXB_) {
        tp1 = tgt[b * MAXB_ * 5 + tid * 5 + 1];
        if (tp1 == 0.0f) atomicMin(&s_nv, tid);
    }
    __syncthreads();
    const int nv  = s_nv;
    const int nvp = (nv + 3) & ~3;

    float contrib = 0.0f;

    float gx = 0, gy = 0, gw = 0, gh = 0, cls = 0;
    int bn = 0, gi = 0, gj = 0;
    if (tid < nvp) {
        if (tid < nv) {
            const float* tp = tgt + (b * MAXB_ + tid) * 5;
            cls = tp[0];
            gx = tp1 * NW_;  gy = tp[2] * NH_;
            gw = tp[3] * NW_; gh = tp[4] * NH_;
            float best = -1.0f;
            #pragma unroll
            for (int q = 0; q < NANC; q++) {
                float aw = __ldg(&anc[2 * q]), ah = __ldg(&anc[2 * q + 1]);
                float inter = fminf(aw, gw) * fminf(ah, gh);
                float r = inter / (aw * ah + gw * gh - inter);
                if (r > best) { best = r; bn = q; }
            }
            gi = min(max((int)gx, 0), NW_ - 1);
            gj = min(max((int)gy, 0), NH_ - 1);
            s_cell[tid] = (bn * NH_ + gj) * NW_ + gi;
            s_b4[tid] = make_float4(gx - 0.5f * gw, gx + 0.5f * gw,
                                    gy - 0.5f * gh, gy + 0.5f * gh);
            s_g2[tid] = K_ * gw * gh;
        } else {
            s_b4[tid] = make_float4(1e30f, -1e30f, 1e30f, -1e30f);
            s_g2[tid] = 1e30f;   // never triggers
        }
    }
    __syncthreads();

    // ---- Object-cell correction (blocks with x==0 only) ----
    if (blockIdx.x == 0 && tid < nv) {
        bool winner = true;            // last-writer-wins scatter semantics
        for (int u = tid + 1; u < nv; u++)
            if (s_cell[u] == s_cell[tid]) winner = false;
        if (winner) {
            const float* op = out + ((size_t)(b * NANC + bn)) * NCH * SPATIAL
                              + gj * NW_ + gi;
            float o0 = op[0], o1 = op[SPATIAL], o2 = op[2 * SPATIAL],
                  o3 = op[3 * SPATIAL], o4 = op[4 * SPATIAL];
            float aw = __ldg(&anc[2 * bn]), ah = __ldg(&anc[2 * bn + 1]);

            float x = sigm(o0), y = sigm(o1), conf = sigm(o4);
            float px = x + (float)gi, py = y + (float)gj;
            float pw = __expf(o2) * aw, ph = __expf(o3) * ah;
            float pxl = px - 0.5f * pw, pxr = px + 0.5f * pw;
            float pyl = py - 0.5f * ph, pyr = py + 0.5f * ph;
            float c0 = K_ * pw * ph;
            int over = 0;
            for (int u = 0; u < nv; u++) {
                float4 g = s_b4[u];
                float cw = fminf(pxr, g.y) - fmaxf(pxl, g.x);
                float ch = fminf(pyr, g.w) - fmaxf(pyl, g.z);
                if (cw > 0.0f && ch > 0.0f && cw * ch > c0 + s_g2[u]) over = 1;
            }
            float dxn = x - 0.5f, dyn = y - 0.5f;
            float noobj = 0.5f * (dxn * dxn + dyn * dyn + o2 * o2 + o3 * o3)
                        + (over ? 0.0f : 0.5f * conf * conf);

            float tx = gx - (float)gi, ty = gy - (float)gj;
            float tw = logf(gw / aw), th = logf(gh / ah);
            float tconf = iou_full(gx, gy, gw, gh, px, py, pw, ph);
            float dx = x - tx, dy = y - ty, dw = o2 - tw, dh = o3 - th,
                  dc = conf - tconf;
            float obj = 0.5f * (dx * dx + dy * dy + dw * dw + dh * dh
                                + OBJ_ * dc * dc);
            const float* cp = op + 5 * SPATIAL;
            float mm = -1e30f;
            #pragma unroll
            for (int c = 0; c < NCLS; c++) mm = fmaxf(mm, cp[c * SPATIAL]);
            float s = 0.0f;
            #pragma unroll
            for (int c = 0; c < NCLS; c++) s += expf(cp[c * SPATIAL] - mm);
            obj += (mm + logf(s)) - cp[(int)cls * SPATIAL];

            contrib += obj - noobj;
        }
    }

    // ---- Main noobj loop: 4 cells per thread, GT loop unrolled 4x ----
    if (act) {
        float o0[4] = {v0.x, v0.y, v0.z, v0.w};
        float o1[4] = {v1.x, v1.y, v1.z, v1.w};
        float o2[4] = {v2.x, v2.y, v2.z, v2.w};
        float o3[4] = {v3.x, v3.y, v3.z, v3.w};
        float o4[4] = {v4.x, v4.y, v4.z, v4.w};

        float pxl[4], pxr[4], pyl[4], pyr[4], c0[4], cf2[4], m[4];
        #pragma unroll
        for (int c = 0; c < 4; c++) {
            float x = sigm(o0[c]), y = sigm(o1[c]), conf = sigm(o4[c]);
            int ii = i0 + c, jj = j0;
            if (ii >= NW_) { ii -= NW_; jj++; }
            float px = x + (float)ii, py = y + (float)jj;
            float pw = __expf(o2[c]) * aw0, ph = __expf(o3[c]) * ah0;
            pxl[c] = px - 0.5f * pw; pxr[c] = px + 0.5f * pw;
            pyl[c] = py - 0.5f * ph; pyr[c] = py + 0.5f * ph;
            c0[c] = K_ * pw * ph;
            float dx = x - 0.5f, dy = y - 0.5f;
            contrib += 0.5f * (dx * dx + dy * dy + o2[c] * o2[c] + o3[c] * o3[c]);
            cf2[c] = 0.5f * conf * conf;
            m[c] = -1e30f;
        }

        for (int t = 0; t < nvp; t += 4) {
            #pragma unroll
            for (int u = 0; u < 4; u++) {
                float4 g = s_b4[t + u];
                float g2 = s_g2[t + u];
                #pragma unroll
                for (int c = 0; c < 4; c++) {
                    float cw = fmaxf(fminf(pxr[c], g.y) - fmaxf(pxl[c], g.x), 0.0f);
                    float ch = fmaxf(fminf(pyr[c], g.w) - fmaxf(pyl[c], g.z), 0.0f);
                    m[c] = fmaxf(m[c], fmaf(cw, ch, -g2));
                }
            }
        }
        #pragma unroll
        for (int c = 0; c < 4; c++)
            if (m[c] <= c0[c]) contrib += cf2[c];
    }

    // ---- Block reduce (4 warps) + last-block writeback ----
    #pragma unroll
    for (int o = 16; o > 0; o >>= 1)
        contrib += __shfl_down_sync(0xFFFFFFFFu, contrib, o);
    __shared__ float wsum[4];
    if ((tid & 31) == 0) wsum[tid >> 5] = contrib;
    __syncthreads();
    if (tid == 0) {
        float v = wsum[0] + wsum[1] + wsum[2] + wsum[3];
        atomicAdd(&g_acc, v);
        __threadfence();
        unsigned prev = atomicAdd(&g_cnt, 1u);
        if (prev == NBLK - 1) {
            float total = atomicAdd(&g_acc, 0.0f);
            res[0] = total;
            g_acc = 0.0f;          // reset for next graph replay
            __threadfence();
            g_cnt = 0u;
        }
    }
}

extern "C" void kernel_launch(void* const* d_in, const int* in_sizes, int n_in,
                              void* d_out, int out_size) {
    const float* out = (const float*)d_in[0];
    const float* tgt = (const float*)d_in[1];
    const float* anc = (const float*)d_in[2];
    float* res = (float*)d_out;

    dim3 grid(GRIDX, NB_);
    region_fused<<<grid, TPB>>>(out, tgt, anc, res);
}

// round 5
// speedup vs baseline: 1.0221x; 1.0221x over previous
#include <cuda_runtime.h>
#include <math.h>

#define NCLS   20
#define NANC   5
#define NB_    64
#define NH_    38
#define NW_    38
#define MAXB_  50
#define SPATIAL 1444
#define CPB    7220            // NANC*SPATIAL
#define NGRP   (CPB / 4)       // 1805 groups of 4 cells
#define NCH    25
#define OBJ_   5.0f
#define K_     0.375f          // THRESH/(1+THRESH) = 0.6/1.6
#define TPB    256
#define GRIDX  8               // ceil(1805/256)
#define NBLK   (GRIDX * NB_)   // 512 blocks

// Aggregation state (zero-initialized at load; reset by last block each call)
__device__ float        g_accs[NB_];
__device__ unsigned int g_cnt = 0;

__device__ __forceinline__ float sigm(float v) { return 1.0f / (1.0f + __expf(-v)); }

__device__ __forceinline__ float iou_full(float x1, float y1, float w1, float h1,
                                          float x2, float y2, float w2, float h2) {
    float cw = fminf(x1 + 0.5f * w1, x2 + 0.5f * w2) - fmaxf(x1 - 0.5f * w1, x2 - 0.5f * w2);
    float ch = fminf(y1 + 0.5f * h1, y2 + 0.5f * h2) - fmaxf(y1 - 0.5f * h1, y2 - 0.5f * h2);
    float inter = (cw <= 0.0f || ch <= 0.0f) ? 0.0f : cw * ch;
    float uni = w1 * h1 + w2 * h2 - inter;
    return inter / uni;
}

__global__ void __launch_bounds__(TPB, 4)
region_fused(const float* __restrict__ out,
             const float* __restrict__ tgt,
             const float* __restrict__ anc,
             float* __restrict__ res) {
    const int b = blockIdx.y;
    const int tid = threadIdx.x;

    __shared__ int    s_nv;
    __shared__ float4 s_b4[MAXB_ + 4];
    __shared__ float  s_g2[MAXB_ + 4];
    __shared__ int    s_cell[MAXB_];

    // ---- Issue the big loads FIRST so they overlap the target parse ----
    const int group = blockIdx.x * TPB + tid;
    const bool act = (group < NGRP);
    int a = 0, i0 = 0, j0 = 0;
    float4 v0, v1, v2, v3, v4;
    float aw0 = 0, ah0 = 0;
    if (act) {
        int base = group * 4;
        a = base / SPATIAL;
        int rem = base - a * SPATIAL;
        j0 = rem / NW_;
        i0 = rem - j0 * NW_;
        const float* op = out + ((size_t)(b * NANC + a)) * NCH * SPATIAL + rem;
        v0 = *(const float4*)(op);
        v1 = *(const float4*)(op + SPATIAL);
        v2 = *(const float4*)(op + 2 * SPATIAL);
        v3 = *(const float4*)(op + 3 * SPATIAL);
        v4 = *(const float4*)(op + 4 * SPATIAL);
        aw0 = __ldg(&anc[2 * a]);
        ah0 = __ldg(&anc[2 * a + 1]);
    }

    // ---- Parallel target parse ----
    if (tid == 0) s_nv = MAXB_;
    __syncthreads();
    float tp1 = 0.0f;
    if (tid < MAXB_) {
        tp1 = tgt[b * MAXB_ * 5 + tid * 5 + 1];
        if (tp1 == 0.0f) atomicMin(&s_nv, tid);
    }
    __syncthreads();
    const int nv  = s_nv;
    const int nvp = (nv + 3) & ~3;

    float contrib = 0.0f;

    float gx = 0, gy = 0, gw = 0, gh = 0, cls = 0;
    int bn = 0, gi = 0, gj = 0;
    if (tid < nvp) {
        if (tid < nv) {
            const float* tp = tgt + (b * MAXB_ + tid) * 5;
            cls = tp[0];
            gx = tp1 * NW_;  gy = tp[2] * NH_;
            gw = tp[3] * NW_; gh = tp[4] * NH_;
            float best = -1.0f;
            #pragma unroll
            for (int q = 0; q < NANC; q++) {
                float aw = __ldg(&anc[2 * q]), ah = __ldg(&anc[2 * q + 1]);
                float inter = fminf(aw, gw) * fminf(ah, gh);
                float r = inter / (aw * ah + gw * gh - inter);
                if (r > best) { best = r; bn = q; }
            }
            gi = min(max((int)gx, 0), NW_ - 1);
            gj = min(max((int)gy, 0), NH_ - 1);
            s_cell[tid] = (bn * NH_ + gj) * NW_ + gi;
            s_b4[tid] = make_float4(gx - 0.5f * gw, gx + 0.5f * gw,
                                    gy - 0.5f * gh, gy + 0.5f * gh);
            s_g2[tid] = K_ * gw * gh;
        } else {
            s_b4[tid] = make_float4(1e30f, -1e30f, 1e30f, -1e30f);
            s_g2[tid] = 1e30f;   // never triggers
        }
    }
    __syncthreads();

    // ---- Object-cell correction (blocks with x==0 only) ----
    if (blockIdx.x == 0 && tid < nv) {
        bool winner = true;            // last-writer-wins scatter semantics
        for (int u = tid + 1; u < nv; u++)
            if (s_cell[u] == s_cell[tid]) winner = false;
        if (winner) {
            const float* op = out + ((size_t)(b * NANC + bn)) * NCH * SPATIAL
                              + gj * NW_ + gi;
            float o0 = op[0], o1 = op[SPATIAL], o2 = op[2 * SPATIAL],
                  o3 = op[3 * SPATIAL], o4 = op[4 * SPATIAL];
            float aw = __ldg(&anc[2 * bn]), ah = __ldg(&anc[2 * bn + 1]);

            float x = sigm(o0), y = sigm(o1), conf = sigm(o4);
            float px = x + (float)gi, py = y + (float)gj;
            float pw = __expf(o2) * aw, ph = __expf(o3) * ah;
            float pxl = px - 0.5f * pw, pxr = px + 0.5f * pw;
            float pyl = py - 0.5f * ph, pyr = py + 0.5f * ph;
            float c0 = K_ * pw * ph;
            int over = 0;
            for (int u = 0; u < nv; u++) {
                float4 g = s_b4[u];
                float cw = fminf(pxr, g.y) - fmaxf(pxl, g.x);
                float ch = fminf(pyr, g.w) - fmaxf(pyl, g.z);
                if (cw > 0.0f && ch > 0.0f && cw * ch > c0 + s_g2[u]) over = 1;
            }
            float dxn = x - 0.5f, dyn = y - 0.5f;
            float noobj = 0.5f * (dxn * dxn + dyn * dyn + o2 * o2 + o3 * o3)
                        + (over ? 0.0f : 0.5f * conf * conf);

            float tx = gx - (float)gi, ty = gy - (float)gj;
            float tw = logf(gw / aw), th = logf(gh / ah);
            float tconf = iou_full(gx, gy, gw, gh, px, py, pw, ph);
            float dx = x - tx, dy = y - ty, dw = o2 - tw, dh = o3 - th,
                  dc = conf - tconf;
            float obj = 0.5f * (dx * dx + dy * dy + dw * dw + dh * dh
                                + OBJ_ * dc * dc);
            const float* cp = op + 5 * SPATIAL;
            float mm = -1e30f;
            #pragma unroll
            for (int c = 0; c < NCLS; c++) mm = fmaxf(mm, cp[c * SPATIAL]);
            float s = 0.0f;
            #pragma unroll
            for (int c = 0; c < NCLS; c++) s += expf(cp[c * SPATIAL] - mm);
            obj += (mm + logf(s)) - cp[(int)cls * SPATIAL];

            contrib += obj - noobj;
        }
    }

    // ---- Main noobj loop: 4 cells per thread, GT loop unrolled 4x ----
    if (act) {
        float o0[4] = {v0.x, v0.y, v0.z, v0.w};
        float o1[4] = {v1.x, v1.y, v1.z, v1.w};
        float o2[4] = {v2.x, v2.y, v2.z, v2.w};
        float o3[4] = {v3.x, v3.y, v3.z, v3.w};
        float o4[4] = {v4.x, v4.y, v4.z, v4.w};

        float pxl[4], pxr[4], pyl[4], pyr[4], c0[4], cf2[4], m[4];
        #pragma unroll
        for (int c = 0; c < 4; c++) {
            float x = sigm(o0[c]), y = sigm(o1[c]), conf = sigm(o4[c]);
            int ii = i0 + c, jj = j0;
            if (ii >= NW_) { ii -= NW_; jj++; }
            float px = x + (float)ii, py = y + (float)jj;
            float pw = __expf(o2[c]) * aw0, ph = __expf(o3[c]) * ah0;
            pxl[c] = px - 0.5f * pw; pxr[c] = px + 0.5f * pw;
            pyl[c] = py - 0.5f * ph; pyr[c] = py + 0.5f * ph;
            c0[c] = K_ * pw * ph;
            float dx = x - 0.5f, dy = y - 0.5f;
            contrib += 0.5f * (dx * dx + dy * dy + o2[c] * o2[c] + o3[c] * o3[c]);
            cf2[c] = 0.5f * conf * conf;
            m[c] = -1e30f;
        }

        for (int t = 0; t < nvp; t += 4) {
            #pragma unroll
            for (int u = 0; u < 4; u++) {
                float4 g = s_b4[t + u];
                float g2 = s_g2[t + u];
                #pragma unroll
                for (int c = 0; c < 4; c++) {
                    float cw = fmaxf(fminf(pxr[c], g.y) - fmaxf(pxl[c], g.x), 0.0f);
                    float ch = fmaxf(fminf(pyr[c], g.w) - fmaxf(pyl[c], g.z), 0.0f);
                    m[c] = fmaxf(m[c], fmaf(cw, ch, -g2));
                }
            }
        }
        #pragma unroll
        for (int c = 0; c < 4; c++)
            if (m[c] <= c0[c]) contrib += cf2[c];
    }

    // ---- Block reduce (8 warps) + per-batch atomic + last-block writeback ----
    #pragma unroll
    for (int o = 16; o > 0; o >>= 1)
        contrib += __shfl_down_sync(0xFFFFFFFFu, contrib, o);
    __shared__ float wsum[8];
    if ((tid & 31) == 0) wsum[tid >> 5] = contrib;
    __syncthreads();
    if (tid == 0) {
        float v = 0.0f;
        #pragma unroll
        for (int q = 0; q < 8; q++) v += wsum[q];
        atomicAdd(&g_accs[b], v);           // 8-way concurrency per address
        __threadfence();
        unsigned prev = atomicAdd(&g_cnt, 1u);
        if (prev == NBLK - 1) {
            __threadfence();                // acquire all g_accs writes
            float total = 0.0f;
            #pragma unroll
            for (int q = 0; q < NB_; q++) {
                total += g_accs[q];
                g_accs[q] = 0.0f;           // reset for next graph replay
            }
            res[0] = total;
            __threadfence();
            g_cnt = 0u;
        }
    }
}

extern "C" void kernel_launch(void* const* d_in, const int* in_sizes, int n_in,
                              void* d_out, int out_size) {
    const float* out = (const float*)d_in[0];
    const float* tgt = (const float*)d_in[1];
    const float* anc = (const float*)d_in[2];
    float* res = (float*)d_out;

    dim3 grid(GRIDX, NB_);
    region_fused<<<grid, TPB>>>(out, tgt, anc, res);
}